// round 3
// baseline (speedup 1.0000x reference)
#include <cuda_runtime.h>
#include <cuda_bf16.h>
#include <cstdint>

// ============================================================================
//   x : (3, 8192) fp32   W1 : (8192, 64)   W2 : (64, 64)   W3 : (64, 1)
//   out = mean(per_row MLP(corr)) - regu2*sum(x2) - regu*sum(exp(x2/(2 rl^2)))
//   corr[i,j] = sum_c x[c,(i+j)%N] * x[c,i]
//
//   Fused: corr tiles built IN REGISTERS as bf16 A-fragments feeding
//   mma.sync m16n8k16 (base ISA; tcgen05 unavailable: ptx target is sm_103).
//   Band kept in SMEM twice (normal + shifted-by-1) so every per-thread
//   float2 load is 8B-aligned regardless of row parity.
// ============================================================================
#define NTOK 8192
#define KHALF 4096
#define BANDLEN 4224                 // 4096 + 128(row span) + slack

__device__ double g_acc[3];                               // sum_x2, sum_exp, sum_per_row
__device__ __align__(16) float g_partial[2 * 64 * NTOK];  // [kh][f][row]
__device__ __align__(16) uint32_t g_w1p[512 * 32 * 16];   // [ks][lane][nt*2+r] bf16x2 frags

__device__ __forceinline__ uint32_t pack_bf16x2(float lo, float hi) {
    uint32_t r;
    asm("cvt.rn.bf16x2.f32 %0, %1, %2;" : "=r"(r) : "f"(hi), "f"(lo));
    return r;
}
__device__ __forceinline__ float elu1(float v) { return v > 0.f ? v : expm1f(v); }

#define MMA_BF16(d0,d1,d2,d3,a0,a1,a2,a3,b0,b1) \
    asm volatile("mma.sync.aligned.m16n8k16.row.col.f32.bf16.bf16.f32 " \
                 "{%0,%1,%2,%3}, {%4,%5,%6,%7}, {%8,%9}, {%0,%1,%2,%3};" \
                 : "+f"(d0), "+f"(d1), "+f"(d2), "+f"(d3) \
                 : "r"(a0), "r"(a1), "r"(a2), "r"(a3), "r"(b0), "r"(b1))

// ---------------------------------------------------------------------------
// K0: zero accumulators
// ---------------------------------------------------------------------------
__global__ void init_kernel() {
    if (threadIdx.x < 3) g_acc[threadIdx.x] = 0.0;
}

// ---------------------------------------------------------------------------
// K1: pre-pack W1 into per-(k-step, lane) m16n8k16 B fragments (bf16x2).
//   b_r (r=0,1): k = ks*16 + (lane%4)*2 + r*8 + {0,1}, n = nt*8 + lane/4
// ---------------------------------------------------------------------------
__global__ void w1prep_kernel(const float* __restrict__ W1) {
    const int idx = blockIdx.x * 256 + threadIdx.x;       // 0 .. 262143
    const int ks = idx >> 9;
    const int rest = idx & 511;
    const int lane = rest >> 4;
    const int q = rest & 15;
    const int nt = q >> 1, r = q & 1;
    const int k = ks * 16 + (lane & 3) * 2 + r * 8;
    const int n = nt * 8 + (lane >> 2);
    g_w1p[idx] = pack_bf16x2(W1[k * 64 + n], W1[(k + 1) * 64 + n]);
}

// ---------------------------------------------------------------------------
// K2: regularization reductions
// ---------------------------------------------------------------------------
__global__ void reg_kernel(const float* __restrict__ x, const float* __restrict__ rl_p) {
    __shared__ float s1[32], s2[32];
    const int i = blockIdx.x * 1024 + threadIdx.x;
    const float a = x[i], b = x[NTOK + i], c = x[2 * NTOK + i];
    float x2 = fmaf(a, a, fmaf(b, b, c * c));
    const float rl = rl_p[0];
    float e = expf(x2 / (2.f * rl * rl));
    #pragma unroll
    for (int o = 16; o > 0; o >>= 1) {
        x2 += __shfl_down_sync(0xFFFFFFFFu, x2, o);
        e  += __shfl_down_sync(0xFFFFFFFFu, e, o);
    }
    const int warp = threadIdx.x >> 5, lane = threadIdx.x & 31;
    if (lane == 0) { s1[warp] = x2; s2[warp] = e; }
    __syncthreads();
    if (warp == 0) {
        float v1 = s1[lane], v2 = s2[lane];
        #pragma unroll
        for (int o = 16; o > 0; o >>= 1) {
            v1 += __shfl_down_sync(0xFFFFFFFFu, v1, o);
            v2 += __shfl_down_sync(0xFFFFFFFFu, v2, o);
        }
        if (lane == 0) {
            atomicAdd(&g_acc[0], (double)v1);
            atomicAdd(&g_acc[1], (double)v2);
        }
    }
}

// ---------------------------------------------------------------------------
// K3: fused corr-build (registers) + mma.sync bf16 GEMM  (preact = corr @ W1)
//   grid = 128: (i-tile of 128 rows) x (K-half of 4096)
//   SMEM: even copy [3][BANDLEN] then odd copy [3][BANDLEN] (odd[o]=band[o+1]).
//   Thread pair base b = warp*16 + g + 2t; parity p = g&1. Reads go through
//   copy p at element (b - p), always 8B-aligned.
// ---------------------------------------------------------------------------
__global__ __launch_bounds__(256, 1) void gemm_kernel(const float* __restrict__ x) {
    extern __shared__ float band[];                // [2][3][BANDLEN]
    const int tid = threadIdx.x, warp = tid >> 5, lane = tid & 31;
    const int g = lane >> 2, t = lane & 3;
    const int it = blockIdx.x >> 1, kh = blockIdx.x & 1;
    const int i0 = it * 128, jbase = kh * KHALF;

    // stage band: even copy = x[c][(i0+jbase+o)&8191], odd copy shifted by 1
    for (int o = tid; o < BANDLEN; o += 256) {
        const int s0 = (i0 + jbase + o) & (NTOK - 1);
        const int s1 = (i0 + jbase + o + 1) & (NTOK - 1);
        band[o]                   = x[s0];
        band[BANDLEN + o]         = x[NTOK + s0];
        band[2 * BANDLEN + o]     = x[2 * NTOK + s0];
        band[3 * BANDLEN + o]     = x[s1];
        band[4 * BANDLEN + o]     = x[NTOK + s1];
        band[5 * BANDLEN + o]     = x[2 * NTOK + s1];
    }
    // per-thread row scalars (rows g and g+8 of this warp's 16-row strip)
    const int r0 = i0 + warp * 16 + g;
    const float x00 = x[r0],     x01 = x[NTOK + r0],     x02 = x[2 * NTOK + r0];
    const float x10 = x[r0 + 8], x11 = x[NTOK + r0 + 8], x12 = x[2 * NTOK + r0 + 8];
    __syncthreads();

    // aligned band pointers (parity-corrected)
    const int par = g & 1;
    const int ib = warp * 16 + g + 2 * t - par;          // even
    const float* sb = band + (par ? 3 * BANDLEN : 0);
    const float2* b0p = (const float2*)(sb + ib);
    const float2* b1p = (const float2*)(sb + BANDLEN + ib);
    const float2* b2p = (const float2*)(sb + 2 * BANDLEN + ib);

    // W1 fragment pointer: uint4 index = ks_global*128 + lane*4
    const uint4* bp = (const uint4*)g_w1p + (size_t)(kh * 256) * 128 + lane * 4;

    float acc[8][4];
    #pragma unroll
    for (int nt = 0; nt < 8; nt++)
        #pragma unroll
        for (int k = 0; k < 4; k++) acc[nt][k] = 0.f;

    // carried band pairs (offset +16 of current step == +0 of next)
    float2 c0 = b0p[0], c1 = b1p[0], c2 = b2p[0];

    #pragma unroll 2
    for (int ks = 0; ks < 256; ks++) {
        const int e8 = ks * 8 + 4;                        // float2 index of +8
        const float2 m0 = b0p[e8],     m1 = b1p[e8],     m2 = b2p[e8];      // +8
        const float2 n0 = b0p[e8 + 4], n1 = b1p[e8 + 4], n2 = b2p[e8 + 4];  // +16

        const float p0lo = fmaf(x00, c0.x, fmaf(x01, c1.x, x02 * c2.x));
        const float p0hi = fmaf(x00, c0.y, fmaf(x01, c1.y, x02 * c2.y));
        const float p1lo = fmaf(x00, m0.x, fmaf(x01, m1.x, x02 * m2.x));
        const float p1hi = fmaf(x00, m0.y, fmaf(x01, m1.y, x02 * m2.y));
        const float q0lo = fmaf(x10, m0.x, fmaf(x11, m1.x, x12 * m2.x));
        const float q0hi = fmaf(x10, m0.y, fmaf(x11, m1.y, x12 * m2.y));
        const float q1lo = fmaf(x10, n0.x, fmaf(x11, n1.x, x12 * n2.x));
        const float q1hi = fmaf(x10, n0.y, fmaf(x11, n1.y, x12 * n2.y));

        const uint32_t a0 = pack_bf16x2(p0lo, p0hi);      // (g,   k=2t..)
        const uint32_t a1 = pack_bf16x2(q0lo, q0hi);      // (g+8, k=2t..)
        const uint32_t a2 = pack_bf16x2(p1lo, p1hi);      // (g,   k=2t+8..)
        const uint32_t a3 = pack_bf16x2(q1lo, q1hi);      // (g+8, k=2t+8..)

        const uint4 B0 = bp[0], B1 = bp[1], B2 = bp[2], B3 = bp[3];
        bp += 128;

        MMA_BF16(acc[0][0], acc[0][1], acc[0][2], acc[0][3], a0, a1, a2, a3, B0.x, B0.y);
        MMA_BF16(acc[1][0], acc[1][1], acc[1][2], acc[1][3], a0, a1, a2, a3, B0.z, B0.w);
        MMA_BF16(acc[2][0], acc[2][1], acc[2][2], acc[2][3], a0, a1, a2, a3, B1.x, B1.y);
        MMA_BF16(acc[3][0], acc[3][1], acc[3][2], acc[3][3], a0, a1, a2, a3, B1.z, B1.w);
        MMA_BF16(acc[4][0], acc[4][1], acc[4][2], acc[4][3], a0, a1, a2, a3, B2.x, B2.y);
        MMA_BF16(acc[5][0], acc[5][1], acc[5][2], acc[5][3], a0, a1, a2, a3, B2.z, B2.w);
        MMA_BF16(acc[6][0], acc[6][1], acc[6][2], acc[6][3], a0, a1, a2, a3, B3.x, B3.y);
        MMA_BF16(acc[7][0], acc[7][1], acc[7][2], acc[7][3], a0, a1, a2, a3, B3.z, B3.w);

        c0 = n0; c1 = n1; c2 = n2;
    }

    // epilogue: scatter accum frags to g_partial[kh][n][row]
    float* base = g_partial + (size_t)kh * (64 * NTOK);
    #pragma unroll
    for (int nt = 0; nt < 8; nt++) {
        const int n = nt * 8 + 2 * t;
        base[(n    ) * NTOK + r0    ] = acc[nt][0];
        base[(n + 1) * NTOK + r0    ] = acc[nt][1];
        base[(n    ) * NTOK + r0 + 8] = acc[nt][2];
        base[(n + 1) * NTOK + r0 + 8] = acc[nt][3];
    }
}

// ---------------------------------------------------------------------------
// K4: per-row MLP epilogue
// ---------------------------------------------------------------------------
__global__ __launch_bounds__(64) void mlp_kernel(const float* __restrict__ W2,
                                                 const float* __restrict__ W3) {
    __shared__ float w2s[4096];
    __shared__ float w3s[64];
    __shared__ float red[2];
    const int tid = threadIdx.x;
    for (int tv = tid; tv < 4096; tv += 64) w2s[tv] = W2[tv];
    if (tid < 64) w3s[tid] = W3[tid];
    __syncthreads();

    const int row = blockIdx.x * 64 + tid;
    float acc2[64];
    #pragma unroll
    for (int f = 0; f < 64; f++) acc2[f] = 0.f;

    for (int f1 = 0; f1 < 64; f1++) {
        const float pre = g_partial[f1 * NTOK + row] + g_partial[64 * NTOK + f1 * NTOK + row];
        const float z1 = elu1(pre);
        const float4* wrow = (const float4*)(w2s + f1 * 64);
        #pragma unroll
        for (int f2 = 0; f2 < 16; f2++) {
            const float4 w = wrow[f2];
            acc2[4 * f2 + 0] = fmaf(z1, w.x, acc2[4 * f2 + 0]);
            acc2[4 * f2 + 1] = fmaf(z1, w.y, acc2[4 * f2 + 1]);
            acc2[4 * f2 + 2] = fmaf(z1, w.z, acc2[4 * f2 + 2]);
            acc2[4 * f2 + 3] = fmaf(z1, w.w, acc2[4 * f2 + 3]);
        }
    }
    float z3 = 0.f;
    #pragma unroll
    for (int f = 0; f < 64; f++) z3 = fmaf(elu1(acc2[f]), w3s[f], z3);
    float per = elu1(z3);

    #pragma unroll
    for (int o = 16; o > 0; o >>= 1) per += __shfl_down_sync(0xFFFFFFFFu, per, o);
    const int warp = tid >> 5, lane = tid & 31;
    if (lane == 0) red[warp] = per;
    __syncthreads();
    if (tid == 0) atomicAdd(&g_acc[2], (double)(red[0] + red[1]));
}

// ---------------------------------------------------------------------------
// K5: combine
// ---------------------------------------------------------------------------
__global__ void final_kernel(const float* __restrict__ regu2,
                             const float* __restrict__ regu,
                             float* __restrict__ out) {
    out[0] = (float)(g_acc[2] / (double)NTOK
                     - (double)regu2[0] * g_acc[0]
                     - (double)regu[0] * g_acc[1]);
}

// ---------------------------------------------------------------------------
// kernel_launch
//   d_in: 0=x 1=W1 2=W2 3=W3 4=regu2 5=regu 6=regu_length
// ---------------------------------------------------------------------------
extern "C" void kernel_launch(void* const* d_in, const int* in_sizes, int n_in,
                              void* d_out, int out_size) {
    const float* x  = (const float*)d_in[0];
    const float* W1 = (const float*)d_in[1];
    const float* W2 = (const float*)d_in[2];
    const float* W3 = (const float*)d_in[3];
    const float* r2 = (const float*)d_in[4];
    const float* r  = (const float*)d_in[5];
    const float* rl = (const float*)d_in[6];
    float* out = (float*)d_out;

    static const int smem_bytes = 6 * BANDLEN * sizeof(float);   // 101376
    cudaFuncSetAttribute(gemm_kernel, cudaFuncAttributeMaxDynamicSharedMemorySize, smem_bytes);

    init_kernel<<<1, 32>>>();
    w1prep_kernel<<<1024, 256>>>(W1);
    reg_kernel<<<8, 1024>>>(x, rl);
    gemm_kernel<<<128, 256, smem_bytes>>>(x);
    mlp_kernel<<<128, 64>>>(W2, W3);
    final_kernel<<<1, 1>>>(r2, r, out);
}

// round 4
// speedup vs baseline: 1.6358x; 1.6358x over previous
#include <cuda_runtime.h>
#include <cuda_bf16.h>
#include <cstdint>

// ============================================================================
//   x : (3, 8192) fp32   W1 : (8192, 64)   W2 : (64, 64)   W3 : (64, 1)
//   out = mean(per_row MLP(corr)) - regu2*sum(x2) - regu*sum(exp(x2/(2 rl^2)))
//   corr[i,j] = sum_c x[c,(i+j)%N] * x[c,i]
//
//   Fused corr-build (registers) + mma.sync m16n8k16 bf16 (base ISA).
//   R4: 32 rows/warp (2 M-strips sharing band pairs + B frags -> LDS/MMA
//   halved), parity copies bank-shifted by 16 floats (conflict-free).
// ============================================================================
#define NTOK 8192
#define KQUART 2048
#define BANDLEN 2336                     // 2048 + 256 + slack, mult of 32
#define ODD_OFF (3 * BANDLEN + 16)       // +16 floats: disjoint banks vs even

__device__ double g_acc[3];                               // sum_x2, sum_exp, sum_per_row
__device__ unsigned int g_done;                           // mlp completion counter
__device__ __align__(16) float g_partial[4 * 64 * NTOK];  // [kq][f][row], 8MB
__device__ __align__(16) uint32_t g_w1p[512 * 32 * 16];   // [ks][lane][nt*2+r] bf16x2

__device__ __forceinline__ uint32_t pack_bf16x2(float lo, float hi) {
    uint32_t r;
    asm("cvt.rn.bf16x2.f32 %0, %1, %2;" : "=r"(r) : "f"(hi), "f"(lo));
    return r;
}
__device__ __forceinline__ float elu1(float v) { return v > 0.f ? v : expm1f(v); }

#define MMA_BF16(d0,d1,d2,d3,a0,a1,a2,a3,b0,b1) \
    asm volatile("mma.sync.aligned.m16n8k16.row.col.f32.bf16.bf16.f32 " \
                 "{%0,%1,%2,%3}, {%4,%5,%6,%7}, {%8,%9}, {%0,%1,%2,%3};" \
                 : "+f"(d0), "+f"(d1), "+f"(d2), "+f"(d3) \
                 : "r"(a0), "r"(a1), "r"(a2), "r"(a3), "r"(b0), "r"(b1))

// ---------------------------------------------------------------------------
// K1: W1 -> m16n8k16 B fragments, coalesced via smem transpose.
//   Block b handles ks = 2b, 2b+1 (32 k-rows). Also block 0 zeroes accums.
//   b_r (r=0,1): k = ks*16 + (lane%4)*2 + r*8 + {0,1}, n = nt*8 + lane/4
// ---------------------------------------------------------------------------
__global__ __launch_bounds__(256) void w1prep_kernel(const float* __restrict__ W1) {
    __shared__ float w[2048];
    if (blockIdx.x == 0 && threadIdx.x == 0) {
        g_acc[0] = 0.0; g_acc[1] = 0.0; g_acc[2] = 0.0; g_done = 0u;
    }
    const int b = blockIdx.x, tid = threadIdx.x;
    const float* src = W1 + b * 2048;                 // rows [32b, 32b+32) x 64
    #pragma unroll
    for (int i = 0; i < 8; i++) w[tid + i * 256] = src[tid + i * 256];
    __syncthreads();

    uint32_t o4[4];
    #pragma unroll
    for (int j = 0; j < 4; j++) {
        const int o = tid * 4 + j;                    // 0..1023
        const int ksl = o >> 9;
        const int rest = o & 511;
        const int lane = rest >> 4;
        const int q = rest & 15;
        const int nt = q >> 1, r = q & 1;
        const int k = ksl * 16 + (lane & 3) * 2 + r * 8;
        const int n = nt * 8 + (lane >> 2);
        o4[j] = pack_bf16x2(w[k * 64 + n], w[(k + 1) * 64 + n]);
    }
    ((uint4*)g_w1p)[b * 256 + tid] = make_uint4(o4[0], o4[1], o4[2], o4[3]);
}

// ---------------------------------------------------------------------------
// K2: regularization reductions
// ---------------------------------------------------------------------------
__global__ void reg_kernel(const float* __restrict__ x, const float* __restrict__ rl_p) {
    __shared__ float s1[32], s2[32];
    const int i = blockIdx.x * 1024 + threadIdx.x;
    const float a = x[i], b = x[NTOK + i], c = x[2 * NTOK + i];
    float x2 = fmaf(a, a, fmaf(b, b, c * c));
    const float rl = rl_p[0];
    float e = expf(x2 / (2.f * rl * rl));
    #pragma unroll
    for (int o = 16; o > 0; o >>= 1) {
        x2 += __shfl_down_sync(0xFFFFFFFFu, x2, o);
        e  += __shfl_down_sync(0xFFFFFFFFu, e, o);
    }
    const int warp = threadIdx.x >> 5, lane = threadIdx.x & 31;
    if (lane == 0) { s1[warp] = x2; s2[warp] = e; }
    __syncthreads();
    if (warp == 0) {
        float v1 = s1[lane], v2 = s2[lane];
        #pragma unroll
        for (int o = 16; o > 0; o >>= 1) {
            v1 += __shfl_down_sync(0xFFFFFFFFu, v1, o);
            v2 += __shfl_down_sync(0xFFFFFFFFu, v2, o);
        }
        if (lane == 0) {
            atomicAdd(&g_acc[0], (double)v1);
            atomicAdd(&g_acc[1], (double)v2);
        }
    }
}

// ---------------------------------------------------------------------------
// K3: fused corr-build + mma.sync bf16 GEMM (preact = corr @ W1)
//   grid = 128: (i-tile of 256 rows) x (K-quarter of 2048)
//   warp owns 32 rows = 2 m16-strips at band offsets +0 / +16.
//   Pairs per step: P0..P4 at +0,+8,+16,+24,+32; next step carries P2..P4.
//   -> 2 fresh float2/channel/step (6 LDS.64) feeding 16 HMMAs.
// ---------------------------------------------------------------------------
__global__ __launch_bounds__(256, 1) void gemm_kernel(const float* __restrict__ x) {
    extern __shared__ float band[];                   // even[3][BANDLEN] | pad16 | odd[3][BANDLEN]
    const int tid = threadIdx.x, warp = tid >> 5, lane = tid & 31;
    const int g = lane >> 2, t = lane & 3;
    const int it = blockIdx.x >> 2, kq = blockIdx.x & 3;
    const int i0 = it * 256, jbase = kq * KQUART;

    // stage band: even copy + shifted-by-1 odd copy
    for (int o = tid; o < BANDLEN; o += 256) {
        const int s0 = (i0 + jbase + o) & (NTOK - 1);
        const int s1 = (i0 + jbase + o + 1) & (NTOK - 1);
        band[o]                       = x[s0];
        band[BANDLEN + o]             = x[NTOK + s0];
        band[2 * BANDLEN + o]         = x[2 * NTOK + s0];
        band[ODD_OFF + o]             = x[s1];
        band[ODD_OFF + BANDLEN + o]   = x[NTOK + s1];
        band[ODD_OFF + 2 * BANDLEN + o] = x[2 * NTOK + s1];
    }
    // per-thread row scalars: rows r0, r0+8, r0+16, r0+24
    const int r0 = i0 + warp * 32 + g;
    const float xA0 = x[r0],      xA1 = x[NTOK + r0],      xA2 = x[2 * NTOK + r0];
    const float xB0 = x[r0 + 8],  xB1 = x[NTOK + r0 + 8],  xB2 = x[2 * NTOK + r0 + 8];
    const float xC0 = x[r0 + 16], xC1 = x[NTOK + r0 + 16], xC2 = x[2 * NTOK + r0 + 16];
    const float xD0 = x[r0 + 24], xD1 = x[NTOK + r0 + 24], xD2 = x[2 * NTOK + r0 + 24];
    __syncthreads();

    // parity-corrected aligned pair pointers
    const int par = g & 1;
    const int ib = warp * 32 + g + 2 * t - par;       // even
    const float* sb = band + (par ? ODD_OFF : 0);
    const float2* p0 = (const float2*)(sb + ib);
    const float2* p1 = (const float2*)(sb + BANDLEN + ib);
    const float2* p2 = (const float2*)(sb + 2 * BANDLEN + ib);

    // W1 fragments: uint4 idx = (kq*128 + ks)*128 + lane*4
    const uint4* bp = (const uint4*)g_w1p + (size_t)(kq * 128) * 128 + lane * 4;

    float acc[2][8][4];
    #pragma unroll
    for (int s = 0; s < 2; s++)
        #pragma unroll
        for (int nt = 0; nt < 8; nt++)
            #pragma unroll
            for (int k = 0; k < 4; k++) acc[s][nt][k] = 0.f;

    // carried pairs P0,P1,P2 per channel
    float2 u0 = p0[0], u1 = p0[4], u2 = p0[8];
    float2 v0 = p1[0], v1 = p1[4], v2 = p1[8];
    float2 w0 = p2[0], w1 = p2[4], w2 = p2[8];

    #pragma unroll 2
    for (int ks = 0; ks < 128; ks++) {
        const int e = ks * 8;
        const float2 u3 = p0[e + 12], u4 = p0[e + 16];   // fresh P3, P4
        const float2 v3 = p1[e + 12], v4 = p1[e + 16];
        const float2 w3 = p2[e + 12], w4 = p2[e + 16];

        // dot3 per pair (lo, hi)
        const float d0lo = fmaf(xA0, u0.x, fmaf(xA1, v0.x, xA2 * w0.x));
        const float d0hi = fmaf(xA0, u0.y, fmaf(xA1, v0.y, xA2 * w0.y));
        const float d1lo = fmaf(xA0, u1.x, fmaf(xA1, v1.x, xA2 * w1.x));
        const float d1hi = fmaf(xA0, u1.y, fmaf(xA1, v1.y, xA2 * w1.y));
        const float e1lo = fmaf(xB0, u1.x, fmaf(xB1, v1.x, xB2 * w1.x));
        const float e1hi = fmaf(xB0, u1.y, fmaf(xB1, v1.y, xB2 * w1.y));
        const float e2lo = fmaf(xB0, u2.x, fmaf(xB1, v2.x, xB2 * w2.x));
        const float e2hi = fmaf(xB0, u2.y, fmaf(xB1, v2.y, xB2 * w2.y));
        const float f2lo = fmaf(xC0, u2.x, fmaf(xC1, v2.x, xC2 * w2.x));
        const float f2hi = fmaf(xC0, u2.y, fmaf(xC1, v2.y, xC2 * w2.y));
        const float f3lo = fmaf(xC0, u3.x, fmaf(xC1, v3.x, xC2 * w3.x));
        const float f3hi = fmaf(xC0, u3.y, fmaf(xC1, v3.y, xC2 * w3.y));
        const float h3lo = fmaf(xD0, u3.x, fmaf(xD1, v3.x, xD2 * w3.x));
        const float h3hi = fmaf(xD0, u3.y, fmaf(xD1, v3.y, xD2 * w3.y));
        const float h4lo = fmaf(xD0, u4.x, fmaf(xD1, v4.x, xD2 * w4.x));
        const float h4hi = fmaf(xD0, u4.y, fmaf(xD1, v4.y, xD2 * w4.y));

        // strip0 A-frags (rows g, g+8)
        const uint32_t a0 = pack_bf16x2(d0lo, d0hi);   // (g,   k=2t)
        const uint32_t a1 = pack_bf16x2(e1lo, e1hi);   // (g+8, k=2t)
        const uint32_t a2 = pack_bf16x2(d1lo, d1hi);   // (g,   k=2t+8)
        const uint32_t a3 = pack_bf16x2(e2lo, e2hi);   // (g+8, k=2t+8)
        // strip1 A-frags (rows g+16, g+24)
        const uint32_t c0 = pack_bf16x2(f2lo, f2hi);
        const uint32_t c1 = pack_bf16x2(h3lo, h3hi);
        const uint32_t c2 = pack_bf16x2(f3lo, f3hi);
        const uint32_t c3 = pack_bf16x2(h4lo, h4hi);

        const uint4 B0 = bp[0], B1 = bp[1], B2 = bp[2], B3 = bp[3];
        bp += 128;

        MMA_BF16(acc[0][0][0], acc[0][0][1], acc[0][0][2], acc[0][0][3], a0, a1, a2, a3, B0.x, B0.y);
        MMA_BF16(acc[0][1][0], acc[0][1][1], acc[0][1][2], acc[0][1][3], a0, a1, a2, a3, B0.z, B0.w);
        MMA_BF16(acc[0][2][0], acc[0][2][1], acc[0][2][2], acc[0][2][3], a0, a1, a2, a3, B1.x, B1.y);
        MMA_BF16(acc[0][3][0], acc[0][3][1], acc[0][3][2], acc[0][3][3], a0, a1, a2, a3, B1.z, B1.w);
        MMA_BF16(acc[0][4][0], acc[0][4][1], acc[0][4][2], acc[0][4][3], a0, a1, a2, a3, B2.x, B2.y);
        MMA_BF16(acc[0][5][0], acc[0][5][1], acc[0][5][2], acc[0][5][3], a0, a1, a2, a3, B2.z, B2.w);
        MMA_BF16(acc[0][6][0], acc[0][6][1], acc[0][6][2], acc[0][6][3], a0, a1, a2, a3, B3.x, B3.y);
        MMA_BF16(acc[0][7][0], acc[0][7][1], acc[0][7][2], acc[0][7][3], a0, a1, a2, a3, B3.z, B3.w);

        MMA_BF16(acc[1][0][0], acc[1][0][1], acc[1][0][2], acc[1][0][3], c0, c1, c2, c3, B0.x, B0.y);
        MMA_BF16(acc[1][1][0], acc[1][1][1], acc[1][1][2], acc[1][1][3], c0, c1, c2, c3, B0.z, B0.w);
        MMA_BF16(acc[1][2][0], acc[1][2][1], acc[1][2][2], acc[1][2][3], c0, c1, c2, c3, B1.x, B1.y);
        MMA_BF16(acc[1][3][0], acc[1][3][1], acc[1][3][2], acc[1][3][3], c0, c1, c2, c3, B1.z, B1.w);
        MMA_BF16(acc[1][4][0], acc[1][4][1], acc[1][4][2], acc[1][4][3], c0, c1, c2, c3, B2.x, B2.y);
        MMA_BF16(acc[1][5][0], acc[1][5][1], acc[1][5][2], acc[1][5][3], c0, c1, c2, c3, B2.z, B2.w);
        MMA_BF16(acc[1][6][0], acc[1][6][1], acc[1][6][2], acc[1][6][3], c0, c1, c2, c3, B3.x, B3.y);
        MMA_BF16(acc[1][7][0], acc[1][7][1], acc[1][7][2], acc[1][7][3], c0, c1, c2, c3, B3.z, B3.w);

        u0 = u2; u1 = u3; u2 = u4;
        v0 = v2; v1 = v3; v2 = v4;
        w0 = w2; w1 = w3; w2 = w4;
    }

    // epilogue: scatter to g_partial[kq][n][row]
    float* basep = g_partial + (size_t)kq * (64 * NTOK);
    #pragma unroll
    for (int s = 0; s < 2; s++) {
        const int rA = r0 + 16 * s, rB = rA + 8;
        #pragma unroll
        for (int nt = 0; nt < 8; nt++) {
            const int n = nt * 8 + 2 * t;
            basep[(n    ) * NTOK + rA] = acc[s][nt][0];
            basep[(n + 1) * NTOK + rA] = acc[s][nt][1];
            basep[(n    ) * NTOK + rB] = acc[s][nt][2];
            basep[(n + 1) * NTOK + rB] = acc[s][nt][3];
        }
    }
}

// ---------------------------------------------------------------------------
// K4: per-row MLP epilogue + final combine (last block)
// ---------------------------------------------------------------------------
__global__ __launch_bounds__(64) void mlp_kernel(const float* __restrict__ W2,
                                                 const float* __restrict__ W3,
                                                 const float* __restrict__ regu2,
                                                 const float* __restrict__ regu,
                                                 float* __restrict__ out) {
    __shared__ float w2s[4096];
    __shared__ float w3s[64];
    __shared__ float red[2];
    const int tid = threadIdx.x;
    for (int tv = tid; tv < 4096; tv += 64) w2s[tv] = W2[tv];
    if (tid < 64) w3s[tid] = W3[tid];
    __syncthreads();

    const int row = blockIdx.x * 64 + tid;
    float acc2[64];
    #pragma unroll
    for (int f = 0; f < 64; f++) acc2[f] = 0.f;

    for (int f1 = 0; f1 < 64; f1++) {
        const float pre = g_partial[f1 * NTOK + row]
                        + g_partial[1 * 64 * NTOK + f1 * NTOK + row]
                        + g_partial[2 * 64 * NTOK + f1 * NTOK + row]
                        + g_partial[3 * 64 * NTOK + f1 * NTOK + row];
        const float z1 = elu1(pre);
        const float4* wrow = (const float4*)(w2s + f1 * 64);
        #pragma unroll
        for (int f2 = 0; f2 < 16; f2++) {
            const float4 w = wrow[f2];
            acc2[4 * f2 + 0] = fmaf(z1, w.x, acc2[4 * f2 + 0]);
            acc2[4 * f2 + 1] = fmaf(z1, w.y, acc2[4 * f2 + 1]);
            acc2[4 * f2 + 2] = fmaf(z1, w.z, acc2[4 * f2 + 2]);
            acc2[4 * f2 + 3] = fmaf(z1, w.w, acc2[4 * f2 + 3]);
        }
    }
    float z3 = 0.f;
    #pragma unroll
    for (int f = 0; f < 64; f++) z3 = fmaf(elu1(acc2[f]), w3s[f], z3);
    float per = elu1(z3);

    #pragma unroll
    for (int o = 16; o > 0; o >>= 1) per += __shfl_down_sync(0xFFFFFFFFu, per, o);
    const int warp = tid >> 5, lane = tid & 31;
    if (lane == 0) red[warp] = per;
    __syncthreads();
    if (tid == 0) {
        atomicAdd(&g_acc[2], (double)(red[0] + red[1]));
        __threadfence();
        const unsigned int done = atomicAdd(&g_done, 1u);
        if (done == gridDim.x - 1) {
            const double s0 = atomicAdd(&g_acc[0], 0.0);
            const double s1 = atomicAdd(&g_acc[1], 0.0);
            const double s2 = atomicAdd(&g_acc[2], 0.0);
            out[0] = (float)(s2 / (double)NTOK
                             - (double)regu2[0] * s0
                             - (double)regu[0] * s1);
        }
    }
}

// ---------------------------------------------------------------------------
// kernel_launch   d_in: 0=x 1=W1 2=W2 3=W3 4=regu2 5=regu 6=regu_length
// ---------------------------------------------------------------------------
extern "C" void kernel_launch(void* const* d_in, const int* in_sizes, int n_in,
                              void* d_out, int out_size) {
    const float* x  = (const float*)d_in[0];
    const float* W1 = (const float*)d_in[1];
    const float* W2 = (const float*)d_in[2];
    const float* W3 = (const float*)d_in[3];
    const float* r2 = (const float*)d_in[4];
    const float* r  = (const float*)d_in[5];
    const float* rl = (const float*)d_in[6];
    float* out = (float*)d_out;

    static const int smem_bytes = (6 * BANDLEN + 16) * sizeof(float);   // 56128
    cudaFuncSetAttribute(gemm_kernel, cudaFuncAttributeMaxDynamicSharedMemorySize, smem_bytes);

    w1prep_kernel<<<256, 256>>>(W1);      // also zeroes g_acc / g_done
    reg_kernel<<<8, 1024>>>(x, rl);
    gemm_kernel<<<128, 256, smem_bytes>>>(x);
    mlp_kernel<<<128, 64>>>(W2, W3, r2, r, out);
}